// round 2
// baseline (speedup 1.0000x reference)
#include <cuda_runtime.h>
#include <math.h>

#define NB 16
#define NC 512
#define NHW 1024
#define NHEADS 8
#define HD 64
#define NG 32
#define OC3 1536
#define GN_EPS 1e-5f

// Scratch (static device globals — allocation-free per harness rules)
__device__ float g_xn[(size_t)NB * NC * NHW];    // 33.5 MB
__device__ float g_qkv[(size_t)NB * OC3 * NHW];  // 100.7 MB
__device__ float g_att[(size_t)NB * NC * NHW];   // 33.5 MB

// ---------------------------------------------------------------------------
// GroupNorm: one block per (batch, group). Group data is 16 channels * 1024
// spatial = 16384 contiguous floats.
// ---------------------------------------------------------------------------
__global__ void __launch_bounds__(256) gn_kernel(
    const float* __restrict__ x, const float* __restrict__ gamma,
    const float* __restrict__ beta, float* __restrict__ out) {
  const int bg = blockIdx.x;  // b*NG + g
  const int g = bg & (NG - 1);
  const size_t base = (size_t)bg * (NC / NG) * NHW;  // 16384 per group
  const float* px = x + base;
  float* po = out + base;
  const int tid = threadIdx.x;

  float s = 0.f, q = 0.f;
#pragma unroll
  for (int k = 0; k < 16; k++) {
    float4 v = *(const float4*)(px + (size_t)(tid + k * 256) * 4);
    s += v.x + v.y + v.z + v.w;
    q += v.x * v.x + v.y * v.y + v.z * v.z + v.w * v.w;
  }
#pragma unroll
  for (int off = 16; off; off >>= 1) {
    s += __shfl_xor_sync(0xffffffffu, s, off);
    q += __shfl_xor_sync(0xffffffffu, q, off);
  }
  __shared__ float ss[8], sq[8];
  __shared__ float s_mean, s_inv;
  const int w = tid >> 5;
  if ((tid & 31) == 0) { ss[w] = s; sq[w] = q; }
  __syncthreads();
  if (tid == 0) {
    float ts = 0.f, tq = 0.f;
#pragma unroll
    for (int i = 0; i < 8; i++) { ts += ss[i]; tq += sq[i]; }
    float mean = ts * (1.f / 16384.f);
    float var = tq * (1.f / 16384.f) - mean * mean;
    s_mean = mean;
    s_inv = rsqrtf(var + GN_EPS);
  }
  __syncthreads();
  const float mean = s_mean, inv = s_inv;
#pragma unroll
  for (int k = 0; k < 16; k++) {
    size_t off = (size_t)(tid + k * 256) * 4;
    int c = g * 16 + (int)(off >> 10);
    float ga = gamma[c], be = beta[c];
    float4 v = *(const float4*)(px + off);
    v.x = (v.x - mean) * inv * ga + be;
    v.y = (v.y - mean) * inv * ga + be;
    v.z = (v.z - mean) * inv * ga + be;
    v.w = (v.w - mean) * inv * ga + be;
    *(float4*)(po + off) = v;
  }
}

// ---------------------------------------------------------------------------
// Tiled SIMT GEMM: Y[b][o][t] = sum_c W[o][c] * X[b][c][t] + bias[o] (+R)
// 64x64 tile, BK=16, 256 threads, 4x4 per-thread register tile.
// ---------------------------------------------------------------------------
template <int OC, bool RESID>
__global__ void __launch_bounds__(256) gemm_kernel(
    const float* __restrict__ W, const float* __restrict__ bias,
    const float* __restrict__ X, const float* __restrict__ R,
    float* __restrict__ Y) {
  __shared__ float As[16][68];  // [k][o]
  __shared__ float Bs[16][68];  // [k][t]
  const int b = blockIdx.z;
  const int o0 = blockIdx.y * 64;
  const int t0 = blockIdx.x * 64;
  const int tid = threadIdx.x;
  const int tx = tid & 15, ty = tid >> 4;
  const float* Xb = X + (size_t)b * NC * NHW;
  const int ar = tid >> 2, ak = (tid & 3) * 4;

  float acc[4][4] = {};
  for (int c0 = 0; c0 < NC; c0 += 16) {
    float4 a4 = *(const float4*)(W + (size_t)(o0 + ar) * NC + c0 + ak);
    As[ak + 0][ar] = a4.x;
    As[ak + 1][ar] = a4.y;
    As[ak + 2][ar] = a4.z;
    As[ak + 3][ar] = a4.w;
    *(float4*)&Bs[ty][tx * 4] =
        *(const float4*)(Xb + (size_t)(c0 + ty) * NHW + t0 + tx * 4);
    __syncthreads();
#pragma unroll
    for (int k = 0; k < 16; k++) {
      float4 a = *(const float4*)&As[k][ty * 4];
      float4 bb = *(const float4*)&Bs[k][tx * 4];
      float av[4] = {a.x, a.y, a.z, a.w};
      float bv[4] = {bb.x, bb.y, bb.z, bb.w};
#pragma unroll
      for (int i = 0; i < 4; i++)
#pragma unroll
        for (int j = 0; j < 4; j++) acc[i][j] += av[i] * bv[j];
    }
    __syncthreads();
  }
#pragma unroll
  for (int i = 0; i < 4; i++) {
    int o = o0 + ty * 4 + i;
    float bi = bias[o];
    size_t off = ((size_t)b * OC + o) * NHW + t0 + tx * 4;
    float4 r;
    r.x = acc[i][0] + bi;
    r.y = acc[i][1] + bi;
    r.z = acc[i][2] + bi;
    r.w = acc[i][3] + bi;
    if (RESID) {
      float4 x4 = *(const float4*)(R + off);
      r.x += x4.x; r.y += x4.y; r.z += x4.z; r.w += x4.w;
    }
    *(float4*)(Y + off) = r;
  }
}

// ---------------------------------------------------------------------------
// Flash attention: one block per (t-tile of 64, b*8+h). Streams K/V in
// 64-wide s tiles with online softmax. All fp32.
// smem: Qs[d][t], Ks[d][s], Vt[s][d], Pt[s][t] — each 64x68 floats.
// ---------------------------------------------------------------------------
__global__ void __launch_bounds__(256) attn_kernel(
    const float* __restrict__ qkv, float* __restrict__ out) {
  extern __shared__ float sm[];
  float* Qs = sm;
  float* Ks = sm + 64 * 68;
  float* Vt = sm + 2 * 64 * 68;
  float* Pt = sm + 3 * 64 * 68;  // also reused as Os[d][t] in epilogue

  const int tid = threadIdx.x;
  const int tx = tid & 15, ty = tid >> 4;
  const int bh = blockIdx.y;
  const int b = bh >> 3, h = bh & 7;
  const int t0 = blockIdx.x * 64;
  const float scale = 0.125f;  // 1/sqrt(64)

  const float* qb = qkv + ((size_t)b * OC3 + h * HD) * NHW;
  const float* kb = qb + (size_t)NC * NHW;
  const float* vb = qb + (size_t)2 * NC * NHW;

  // Load Q tile (scaled) once: Qs[d][t]
#pragma unroll
  for (int it = 0; it < 4; it++) {
    int d = ty + it * 16;
    float4 v = *(const float4*)(qb + (size_t)d * NHW + t0 + tx * 4);
    v.x *= scale; v.y *= scale; v.z *= scale; v.w *= scale;
    *(float4*)&Qs[d * 68 + tx * 4] = v;
  }

  float m[4], l[4], o[4][4];
#pragma unroll
  for (int i = 0; i < 4; i++) {
    m[i] = -1e30f;
    l[i] = 0.f;
#pragma unroll
    for (int j = 0; j < 4; j++) o[i][j] = 0.f;
  }
  __syncthreads();

  for (int s0 = 0; s0 < NHW; s0 += 64) {
    // Load K tile [d][s] and V tile transposed [s][d]
#pragma unroll
    for (int it = 0; it < 4; it++) {
      int d = ty + it * 16;
      *(float4*)&Ks[d * 68 + tx * 4] =
          *(const float4*)(kb + (size_t)d * NHW + s0 + tx * 4);
      float4 vv = *(const float4*)(vb + (size_t)d * NHW + s0 + tx * 4);
      Vt[(tx * 4 + 0) * 68 + d] = vv.x;
      Vt[(tx * 4 + 1) * 68 + d] = vv.y;
      Vt[(tx * 4 + 2) * 68 + d] = vv.z;
      Vt[(tx * 4 + 3) * 68 + d] = vv.w;
    }
    __syncthreads();

    // S = (Q*scale)^T K  — 4x4 per thread, rows t=ty*4+i, cols s=tx*4+j
    float sc[4][4] = {};
#pragma unroll 8
    for (int d = 0; d < 64; d++) {
      float4 a = *(const float4*)&Qs[d * 68 + ty * 4];
      float4 bb = *(const float4*)&Ks[d * 68 + tx * 4];
      float av[4] = {a.x, a.y, a.z, a.w};
      float bv[4] = {bb.x, bb.y, bb.z, bb.w};
#pragma unroll
      for (int i = 0; i < 4; i++)
#pragma unroll
        for (int j = 0; j < 4; j++) sc[i][j] += av[i] * bv[j];
    }

    // Online softmax. Row group = 16 lanes sharing ty (same half-warp).
#pragma unroll
    for (int i = 0; i < 4; i++) {
      float mt = fmaxf(fmaxf(sc[i][0], sc[i][1]), fmaxf(sc[i][2], sc[i][3]));
#pragma unroll
      for (int off = 8; off; off >>= 1)
        mt = fmaxf(mt, __shfl_xor_sync(0xffffffffu, mt, off));
      float mn = fmaxf(m[i], mt);
      float fac = __expf(m[i] - mn);
      m[i] = mn;
      float rs = 0.f;
#pragma unroll
      for (int j = 0; j < 4; j++) {
        float p = __expf(sc[i][j] - mn);
        sc[i][j] = p;
        rs += p;
      }
#pragma unroll
      for (int off = 8; off; off >>= 1)
        rs += __shfl_xor_sync(0xffffffffu, rs, off);
      l[i] = l[i] * fac + rs;
#pragma unroll
      for (int j = 0; j < 4; j++) o[i][j] *= fac;
    }

    // Write P transposed: Pt[s][t]
#pragma unroll
    for (int j = 0; j < 4; j++) {
      float4 p4 = make_float4(sc[0][j], sc[1][j], sc[2][j], sc[3][j]);
      *(float4*)&Pt[(tx * 4 + j) * 68 + ty * 4] = p4;
    }
    __syncthreads();

    // O[t][d] += sum_s P[t][s] V[d][s] ; rows t=ty*4+i, cols d=tx*4+j
#pragma unroll 8
    for (int s = 0; s < 64; s++) {
      float4 a = *(const float4*)&Pt[s * 68 + ty * 4];
      float4 bb = *(const float4*)&Vt[s * 68 + tx * 4];
      float av[4] = {a.x, a.y, a.z, a.w};
      float bv[4] = {bb.x, bb.y, bb.z, bb.w};
#pragma unroll
      for (int i = 0; i < 4; i++)
#pragma unroll
        for (int j = 0; j < 4; j++) o[i][j] += av[i] * bv[j];
    }
    __syncthreads();  // protects Ks/Vt/Pt for next iteration (and epilogue)
  }

  // Epilogue: normalize, stage Os[d][t] into Pt, coalesced global write.
  float inv[4];
#pragma unroll
  for (int i = 0; i < 4; i++) inv[i] = 1.f / l[i];
#pragma unroll
  for (int j = 0; j < 4; j++) {
    float4 o4 = make_float4(o[0][j] * inv[0], o[1][j] * inv[1],
                            o[2][j] * inv[2], o[3][j] * inv[3]);
    *(float4*)&Pt[(tx * 4 + j) * 68 + ty * 4] = o4;
  }
  __syncthreads();
#pragma unroll
  for (int it = 0; it < 4; it++) {
    int d = ty + it * 16;
    float4 v = *(const float4*)&Pt[d * 68 + tx * 4];
    *(float4*)(out + ((size_t)b * NC + h * HD + d) * NHW + t0 + tx * 4) = v;
  }
}

// ---------------------------------------------------------------------------
extern "C" void kernel_launch(void* const* d_in, const int* in_sizes, int n_in,
                              void* d_out, int out_size) {
  const float* x = (const float*)d_in[0];
  const float* gn_gamma = (const float*)d_in[1];
  const float* gn_beta = (const float*)d_in[2];
  const float* qkv_w = (const float*)d_in[3];
  const float* qkv_b = (const float*)d_in[4];
  const float* proj_w = (const float*)d_in[5];
  const float* proj_b = (const float*)d_in[6];
  float* out = (float*)d_out;

  float *xn, *qkvp, *att;
  cudaGetSymbolAddress((void**)&xn, g_xn);
  cudaGetSymbolAddress((void**)&qkvp, g_qkv);
  cudaGetSymbolAddress((void**)&att, g_att);

  const int SMEMB = 4 * 64 * 68 * (int)sizeof(float);  // 69632 B
  cudaFuncSetAttribute(attn_kernel, cudaFuncAttributeMaxDynamicSharedMemorySize,
                       SMEMB);

  // 1) GroupNorm
  gn_kernel<<<NB * NG, 256>>>(x, gn_gamma, gn_beta, xn);
  // 2) QKV 1x1 conv: [1536,512] x [512,1024] per batch
  gemm_kernel<OC3, false>
      <<<dim3(16, 24, NB), 256>>>(qkv_w, qkv_b, xn, nullptr, qkvp);
  // 3) Flash attention per (t-tile, b, head)
  attn_kernel<<<dim3(16, NB * NHEADS), 256, SMEMB>>>(qkvp, att);
  // 4) Proj + bias + residual
  gemm_kernel<NC, true>
      <<<dim3(16, 8, NB), 256>>>(proj_w, proj_b, att, x, out);
}

// round 5
// speedup vs baseline: 1.0733x; 1.0733x over previous
#include <cuda_runtime.h>
#include <math.h>

#define NB 16
#define NC 512
#define NHW 1024
#define NHEADS 8
#define HD 64
#define NG 32
#define OC3 1536
#define GN_EPS 1e-5f

// Scratch (static device globals — allocation-free per harness rules)
__device__ float g_xn[(size_t)NB * NC * NHW];    // 33.5 MB
__device__ float g_qkv[(size_t)NB * OC3 * NHW];  // 100.7 MB
__device__ float g_att[(size_t)NB * NC * NHW];   // 33.5 MB

// ---------------------------------------------------------------------------
// GroupNorm: one block per (batch, group). 16 ch * 1024 sp = 16384 floats.
// ---------------------------------------------------------------------------
__global__ void __launch_bounds__(256) gn_kernel(
    const float* __restrict__ x, const float* __restrict__ gamma,
    const float* __restrict__ beta, float* __restrict__ out) {
  const int bg = blockIdx.x;
  const int g = bg & (NG - 1);
  const size_t base = (size_t)bg * (NC / NG) * NHW;
  const float* px = x + base;
  float* po = out + base;
  const int tid = threadIdx.x;

  float s = 0.f, q = 0.f;
#pragma unroll
  for (int k = 0; k < 16; k++) {
    float4 v = *(const float4*)(px + (size_t)(tid + k * 256) * 4);
    s += v.x + v.y + v.z + v.w;
    q += v.x * v.x + v.y * v.y + v.z * v.z + v.w * v.w;
  }
#pragma unroll
  for (int off = 16; off; off >>= 1) {
    s += __shfl_xor_sync(0xffffffffu, s, off);
    q += __shfl_xor_sync(0xffffffffu, q, off);
  }
  __shared__ float ss[8], sq[8];
  __shared__ float s_mean, s_inv;
  const int w = tid >> 5;
  if ((tid & 31) == 0) { ss[w] = s; sq[w] = q; }
  __syncthreads();
  if (tid == 0) {
    float ts = 0.f, tq = 0.f;
#pragma unroll
    for (int i = 0; i < 8; i++) { ts += ss[i]; tq += sq[i]; }
    float mean = ts * (1.f / 16384.f);
    float var = tq * (1.f / 16384.f) - mean * mean;
    s_mean = mean;
    s_inv = rsqrtf(var + GN_EPS);
  }
  __syncthreads();
  const float mean = s_mean, inv = s_inv;
#pragma unroll
  for (int k = 0; k < 16; k++) {
    size_t off = (size_t)(tid + k * 256) * 4;
    int c = g * 16 + (int)(off >> 10);
    float ga = gamma[c], be = beta[c];
    float4 v = *(const float4*)(px + off);
    v.x = (v.x - mean) * inv * ga + be;
    v.y = (v.y - mean) * inv * ga + be;
    v.z = (v.z - mean) * inv * ga + be;
    v.w = (v.w - mean) * inv * ga + be;
    *(float4*)(po + off) = v;
  }
}

// ---------------------------------------------------------------------------
// GEMM: Y[b][o][t] = sum_c W[o][c] X[b][c][t] + bias[o] (+R)
// 128x128 tile, BK=16, 256 threads, 8x8 microtile, smem double-buffered.
// ---------------------------------------------------------------------------
#define SA 132
#define SB 132

template <int OC, bool RESID>
__global__ void __launch_bounds__(256, 1) gemm_kernel(
    const float* __restrict__ W, const float* __restrict__ bias,
    const float* __restrict__ X, const float* __restrict__ R,
    float* __restrict__ Y) {
  __shared__ float As[2][16 * SA];  // [k][o]
  __shared__ float Bs[2][16 * SB];  // [k][t]
  const int b = blockIdx.z;
  const int o0 = blockIdx.y * 128;
  const int t0 = blockIdx.x * 128;
  const int tid = threadIdx.x;
  const int tx = tid & 15, ty = tid >> 4;
  const float* Xb = X + (size_t)b * NC * NHW;

  const int ma = tid >> 2;           // 0..63 (A row within tile; +64 second)
  const int kqa = (tid & 3) * 4;     // A k-float4 start
  const int kb = tid >> 5;           // 0..7 (B k row; +8 second)
  const int nb = (tid & 31) * 4;     // B col float4

  const float* Aptr = W + (size_t)(o0 + ma) * NC + kqa;
  const float* Bptr = Xb + (size_t)kb * NHW + t0 + nb;

  float4 a0r = *(const float4*)(Aptr);
  float4 a1r = *(const float4*)(Aptr + (size_t)64 * NC);
  float4 b0r = *(const float4*)(Bptr);
  float4 b1r = *(const float4*)(Bptr + (size_t)8 * NHW);

  // store tile 0
  {
    float* A_ = As[0]; float* B_ = Bs[0];
    A_[(kqa + 0) * SA + ma] = a0r.x;
    A_[(kqa + 1) * SA + ma] = a0r.y;
    A_[(kqa + 2) * SA + ma] = a0r.z;
    A_[(kqa + 3) * SA + ma] = a0r.w;
    A_[(kqa + 0) * SA + ma + 64] = a1r.x;
    A_[(kqa + 1) * SA + ma + 64] = a1r.y;
    A_[(kqa + 2) * SA + ma + 64] = a1r.z;
    A_[(kqa + 3) * SA + ma + 64] = a1r.w;
    *(float4*)&B_[kb * SB + nb] = b0r;
    *(float4*)&B_[(kb + 8) * SB + nb] = b1r;
  }
  __syncthreads();

  float acc[8][8] = {};
#pragma unroll 1
  for (int bk = 0; bk < NC / 16; ++bk) {
    const int cur = bk & 1;
    if (bk < NC / 16 - 1) {
      const float* Ap = Aptr + (bk + 1) * 16;
      a0r = *(const float4*)(Ap);
      a1r = *(const float4*)(Ap + (size_t)64 * NC);
      const float* Bp = Bptr + (size_t)(bk + 1) * 16 * NHW;
      b0r = *(const float4*)(Bp);
      b1r = *(const float4*)(Bp + (size_t)8 * NHW);
    }
    const float* A_ = As[cur];
    const float* B_ = Bs[cur];
#pragma unroll
    for (int k = 0; k < 16; ++k) {
      float4 a0 = *(const float4*)&A_[k * SA + ty * 8];
      float4 a1 = *(const float4*)&A_[k * SA + ty * 8 + 4];
      float4 b0 = *(const float4*)&B_[k * SB + tx * 8];
      float4 b1 = *(const float4*)&B_[k * SB + tx * 8 + 4];
      float av[8] = {a0.x, a0.y, a0.z, a0.w, a1.x, a1.y, a1.z, a1.w};
      float bv[8] = {b0.x, b0.y, b0.z, b0.w, b1.x, b1.y, b1.z, b1.w};
#pragma unroll
      for (int i = 0; i < 8; i++)
#pragma unroll
        for (int j = 0; j < 8; j++) acc[i][j] += av[i] * bv[j];
    }
    if (bk < NC / 16 - 1) {
      const int nxt = cur ^ 1;
      float* A_n = As[nxt]; float* B_n = Bs[nxt];
      A_n[(kqa + 0) * SA + ma] = a0r.x;
      A_n[(kqa + 1) * SA + ma] = a0r.y;
      A_n[(kqa + 2) * SA + ma] = a0r.z;
      A_n[(kqa + 3) * SA + ma] = a0r.w;
      A_n[(kqa + 0) * SA + ma + 64] = a1r.x;
      A_n[(kqa + 1) * SA + ma + 64] = a1r.y;
      A_n[(kqa + 2) * SA + ma + 64] = a1r.z;
      A_n[(kqa + 3) * SA + ma + 64] = a1r.w;
      *(float4*)&B_n[kb * SB + nb] = b0r;
      *(float4*)&B_n[(kb + 8) * SB + nb] = b1r;
      __syncthreads();
    }
  }

#pragma unroll
  for (int i = 0; i < 8; i++) {
    const int o = o0 + ty * 8 + i;
    const float bi = bias[o];
    size_t off = ((size_t)b * OC + o) * NHW + t0 + tx * 8;
    float4 r0, r1;
    r0.x = acc[i][0] + bi; r0.y = acc[i][1] + bi;
    r0.z = acc[i][2] + bi; r0.w = acc[i][3] + bi;
    r1.x = acc[i][4] + bi; r1.y = acc[i][5] + bi;
    r1.z = acc[i][6] + bi; r1.w = acc[i][7] + bi;
    if (RESID) {
      float4 x0 = *(const float4*)(R + off);
      float4 x1 = *(const float4*)(R + off + 4);
      r0.x += x0.x; r0.y += x0.y; r0.z += x0.z; r0.w += x0.w;
      r1.x += x1.x; r1.y += x1.y; r1.z += x1.z; r1.w += x1.w;
    }
    *(float4*)(Y + off) = r0;
    *(float4*)(Y + off + 4) = r1;
  }
}

// ---------------------------------------------------------------------------
// Flash attention: 128-query tile per block, stream keys in 128-wide tiles.
// S-phase: 8x8 microtile over k=64.  PV-phase: 8x4 microtile over s=128.
// All tile strides are multiples of 4 floats -> every float4 access is
// 16B-aligned (R2's odd strides trapped with "misaligned address").
// ---------------------------------------------------------------------------
#define SQ 132
#define SK 132
#define SV 68
#define SP 132

__global__ void __launch_bounds__(256, 1) attn_kernel(
    const float* __restrict__ qkv, float* __restrict__ out) {
  extern __shared__ float sm[];
  float* Qs = sm;                    // [64][SQ]
  float* Ks = Qs + 64 * SQ;          // [64][SK]
  float* Vt = Ks + 64 * SK;          // [128][SV]  (Vt[s][d])
  float* Pt = Vt + 128 * SV;         // [128][SP]  (Pt[s][t]); reused epilogue

  const int tid = threadIdx.x;
  const int tx = tid & 15, ty = tid >> 4;
  const int warp = tid >> 5, lane = tid & 31;
  const int bh = blockIdx.y;
  const int b = bh >> 3, h = bh & 7;
  const int t0 = blockIdx.x * 128;
  const float scale = 0.125f;

  const float* qb = qkv + ((size_t)b * OC3 + h * HD) * NHW;
  const float* kb_ = qb + (size_t)NC * NHW;
  const float* vb = qb + (size_t)2 * NC * NHW;

  // Load Q tile (scaled): Qs[d][t]
#pragma unroll
  for (int it = 0; it < 8; it++) {
    const int d = warp * 8 + it;
    float4 v = *(const float4*)(qb + (size_t)d * NHW + t0 + lane * 4);
    v.x *= scale; v.y *= scale; v.z *= scale; v.w *= scale;
    *(float4*)&Qs[d * SQ + lane * 4] = v;
  }

  float m[8], l[8], o_[8][4];
#pragma unroll
  for (int i = 0; i < 8; i++) {
    m[i] = -1e30f; l[i] = 0.f;
#pragma unroll
    for (int jj = 0; jj < 4; jj++) o_[i][jj] = 0.f;
  }
  __syncthreads();

#pragma unroll 1
  for (int s0 = 0; s0 < NHW; s0 += 128) {
    // Load K tile [d][s] and V tile transposed [s][d]
#pragma unroll
    for (int it = 0; it < 8; it++) {
      const int d = warp * 8 + it;
      *(float4*)&Ks[d * SK + lane * 4] =
          *(const float4*)(kb_ + (size_t)d * NHW + s0 + lane * 4);
      float4 vv = *(const float4*)(vb + (size_t)d * NHW + s0 + lane * 4);
      Vt[(lane * 4 + 0) * SV + d] = vv.x;
      Vt[(lane * 4 + 1) * SV + d] = vv.y;
      Vt[(lane * 4 + 2) * SV + d] = vv.z;
      Vt[(lane * 4 + 3) * SV + d] = vv.w;
    }
    __syncthreads();

    // S = Q^T K : rows t=ty*8+i, cols s=tx*8+j
    float sc[8][8] = {};
#pragma unroll 8
    for (int k = 0; k < 64; k++) {
      float4 a0 = *(const float4*)&Qs[k * SQ + ty * 8];
      float4 a1 = *(const float4*)&Qs[k * SQ + ty * 8 + 4];
      float4 b0 = *(const float4*)&Ks[k * SK + tx * 8];
      float4 b1 = *(const float4*)&Ks[k * SK + tx * 8 + 4];
      float av[8] = {a0.x, a0.y, a0.z, a0.w, a1.x, a1.y, a1.z, a1.w};
      float bv[8] = {b0.x, b0.y, b0.z, b0.w, b1.x, b1.y, b1.z, b1.w};
#pragma unroll
      for (int i = 0; i < 8; i++)
#pragma unroll
        for (int j = 0; j < 8; j++) sc[i][j] += av[i] * bv[j];
    }

    // Online softmax (row groups = 16 lanes sharing ty; xor<16 stays in-warp)
#pragma unroll
    for (int i = 0; i < 8; i++) {
      float mt = sc[i][0];
#pragma unroll
      for (int j = 1; j < 8; j++) mt = fmaxf(mt, sc[i][j]);
#pragma unroll
      for (int off = 8; off; off >>= 1)
        mt = fmaxf(mt, __shfl_xor_sync(0xffffffffu, mt, off));
      const float mn = fmaxf(m[i], mt);
      const float fac = __expf(m[i] - mn);
      m[i] = mn;
      float rs = 0.f;
#pragma unroll
      for (int j = 0; j < 8; j++) {
        const float p = __expf(sc[i][j] - mn);
        sc[i][j] = p;
        rs += p;
      }
#pragma unroll
      for (int off = 8; off; off >>= 1)
        rs += __shfl_xor_sync(0xffffffffu, rs, off);
      l[i] = l[i] * fac + rs;
#pragma unroll
      for (int jj = 0; jj < 4; jj++) o_[i][jj] *= fac;
    }

    // Write P transposed: Pt[s][t]
#pragma unroll
    for (int j = 0; j < 8; j++) {
      const int srow = (tx * 8 + j) * SP + ty * 8;
      *(float4*)&Pt[srow] = make_float4(sc[0][j], sc[1][j], sc[2][j], sc[3][j]);
      *(float4*)&Pt[srow + 4] =
          make_float4(sc[4][j], sc[5][j], sc[6][j], sc[7][j]);
    }
    __syncthreads();

    // O[t][d] += P[t][s] V[s][d] : rows t=ty*8+i, cols d=tx*4+jj
#pragma unroll 4
    for (int s = 0; s < 128; s++) {
      float4 a0 = *(const float4*)&Pt[s * SP + ty * 8];
      float4 a1 = *(const float4*)&Pt[s * SP + ty * 8 + 4];
      float4 bvv = *(const float4*)&Vt[s * SV + tx * 4];
      float av[8] = {a0.x, a0.y, a0.z, a0.w, a1.x, a1.y, a1.z, a1.w};
      float bv[4] = {bvv.x, bvv.y, bvv.z, bvv.w};
#pragma unroll
      for (int i = 0; i < 8; i++)
#pragma unroll
        for (int jj = 0; jj < 4; jj++) o_[i][jj] += av[i] * bv[jj];
    }
    __syncthreads();
  }

  // Epilogue: normalize, stage Od[d][t] in Pt, coalesced write.
  float inv[8];
#pragma unroll
  for (int i = 0; i < 8; i++) inv[i] = 1.f / l[i];
#pragma unroll
  for (int jj = 0; jj < 4; jj++)
#pragma unroll
    for (int i = 0; i < 8; i++)
      Pt[(tx * 4 + jj) * SP + ty * 8 + i] = o_[i][jj] * inv[i];
  __syncthreads();
#pragma unroll
  for (int it = 0; it < 8; it++) {
    const int d = warp * 8 + it;
    float4 v = *(const float4*)&Pt[d * SP + lane * 4];
    *(float4*)(out + ((size_t)b * NC + h * HD + d) * NHW + t0 + lane * 4) = v;
  }
}

// ---------------------------------------------------------------------------
extern "C" void kernel_launch(void* const* d_in, const int* in_sizes, int n_in,
                              void* d_out, int out_size) {
  const float* x = (const float*)d_in[0];
  const float* gn_gamma = (const float*)d_in[1];
  const float* gn_beta = (const float*)d_in[2];
  const float* qkv_w = (const float*)d_in[3];
  const float* qkv_b = (const float*)d_in[4];
  const float* proj_w = (const float*)d_in[5];
  const float* proj_b = (const float*)d_in[6];
  float* out = (float*)d_out;

  float *xn, *qkvp, *att;
  cudaGetSymbolAddress((void**)&xn, g_xn);
  cudaGetSymbolAddress((void**)&qkvp, g_qkv);
  cudaGetSymbolAddress((void**)&att, g_att);

  const int SMEMB =
      (64 * SQ + 64 * SK + 128 * SV + 128 * SP) * (int)sizeof(float);  // ~166KB
  cudaFuncSetAttribute(attn_kernel, cudaFuncAttributeMaxDynamicSharedMemorySize,
                       SMEMB);

  gn_kernel<<<NB * NG, 256>>>(x, gn_gamma, gn_beta, xn);
  gemm_kernel<OC3, false>
      <<<dim3(8, 12, NB), 256>>>(qkv_w, qkv_b, xn, nullptr, qkvp);
  attn_kernel<<<dim3(8, NB * NHEADS), 256, SMEMB>>>(qkvp, att);
  gemm_kernel<NC, true>
      <<<dim3(8, 4, NB), 256>>>(proj_w, proj_b, att, x, out);
}

// round 7
// speedup vs baseline: 1.3902x; 1.2953x over previous
#include <cuda_runtime.h>
#include <math.h>
#include <stdint.h>

#define NB 16
#define NC 512
#define NHW 1024
#define NHEADS 8
#define HD 64
#define NG 32
#define OC3 1536
#define GN_EPS 1e-5f

// Scratch (static device globals — allocation-free per harness rules)
__device__ float g_xn[(size_t)NB * NC * NHW];
__device__ float g_qkv[(size_t)NB * OC3 * NHW];
__device__ float g_att[(size_t)NB * NC * NHW];

// ============================ helpers ======================================
__device__ __forceinline__ uint32_t smem_u32(const void* p) {
  uint32_t a;
  asm("{ .reg .u64 t; cvta.to.shared.u64 t, %1; cvt.u32.u64 %0, t; }"
      : "=r"(a) : "l"(p));
  return a;
}
__device__ __forceinline__ uint32_t packbf2(float lo16, float hi16) {
  // result: low 16 bits = bf16(lo16), high 16 bits = bf16(hi16)
  uint32_t r;
  asm("cvt.rn.bf16x2.f32 %0, %1, %2;" : "=r"(r) : "f"(hi16), "f"(lo16));
  return r;
}
__device__ __forceinline__ void ldsm_x4(uint32_t* r, uint32_t addr) {
  asm volatile("ldmatrix.sync.aligned.m8n8.x4.shared.b16 {%0,%1,%2,%3}, [%4];"
               : "=r"(r[0]), "=r"(r[1]), "=r"(r[2]), "=r"(r[3]) : "r"(addr));
}
__device__ __forceinline__ void ldsm_x4_t(uint32_t* r, uint32_t addr) {
  asm volatile(
      "ldmatrix.sync.aligned.m8n8.x4.trans.shared.b16 {%0,%1,%2,%3}, [%4];"
      : "=r"(r[0]), "=r"(r[1]), "=r"(r[2]), "=r"(r[3]) : "r"(addr));
}
__device__ __forceinline__ void mma16816(float* d, const uint32_t* a,
                                         const uint32_t* b) {
  asm volatile(
      "mma.sync.aligned.m16n8k16.row.col.f32.bf16.bf16.f32 "
      "{%0,%1,%2,%3}, {%4,%5,%6,%7}, {%8,%9}, {%0,%1,%2,%3};"
      : "+f"(d[0]), "+f"(d[1]), "+f"(d[2]), "+f"(d[3])
      : "r"(a[0]), "r"(a[1]), "r"(a[2]), "r"(a[3]), "r"(b[0]), "r"(b[1]));
}

// ---------------------------------------------------------------------------
// GroupNorm (unchanged)
// ---------------------------------------------------------------------------
__global__ void __launch_bounds__(256) gn_kernel(
    const float* __restrict__ x, const float* __restrict__ gamma,
    const float* __restrict__ beta, float* __restrict__ out) {
  const int bg = blockIdx.x;
  const int g = bg & (NG - 1);
  const size_t base = (size_t)bg * (NC / NG) * NHW;
  const float* px = x + base;
  float* po = out + base;
  const int tid = threadIdx.x;

  float s = 0.f, q = 0.f;
#pragma unroll
  for (int k = 0; k < 16; k++) {
    float4 v = *(const float4*)(px + (size_t)(tid + k * 256) * 4);
    s += v.x + v.y + v.z + v.w;
    q += v.x * v.x + v.y * v.y + v.z * v.z + v.w * v.w;
  }
#pragma unroll
  for (int off = 16; off; off >>= 1) {
    s += __shfl_xor_sync(0xffffffffu, s, off);
    q += __shfl_xor_sync(0xffffffffu, q, off);
  }
  __shared__ float ss[8], sq[8];
  __shared__ float s_mean, s_inv;
  const int w = tid >> 5;
  if ((tid & 31) == 0) { ss[w] = s; sq[w] = q; }
  __syncthreads();
  if (tid == 0) {
    float ts = 0.f, tq = 0.f;
#pragma unroll
    for (int i = 0; i < 8; i++) { ts += ss[i]; tq += sq[i]; }
    float mean = ts * (1.f / 16384.f);
    float var = tq * (1.f / 16384.f) - mean * mean;
    s_mean = mean;
    s_inv = rsqrtf(var + GN_EPS);
  }
  __syncthreads();
  const float mean = s_mean, inv = s_inv;
#pragma unroll
  for (int k = 0; k < 16; k++) {
    size_t off = (size_t)(tid + k * 256) * 4;
    int c = g * 16 + (int)(off >> 10);
    float ga = gamma[c], be = beta[c];
    float4 v = *(const float4*)(px + off);
    v.x = (v.x - mean) * inv * ga + be;
    v.y = (v.y - mean) * inv * ga + be;
    v.z = (v.z - mean) * inv * ga + be;
    v.w = (v.w - mean) * inv * ga + be;
    *(float4*)(po + off) = v;
  }
}

// ---------------------------------------------------------------------------
// HMMA (mma.sync bf16, split hi/lo fp32) GEMM:
//   Y[b][o][t] = sum_c W[o][c] X[b][c][t] + bias[o] (+R)
// CTA tile 128(o) x 64(t), K-chunk 32. 8 warps = 4(m) x 2(n), warp tile 32x32.
// A smem [128][SAH] halves K-major; B smem [32][SBH] halves K-major rows=c.
// A frags: ldmatrix.x4 (row-major); B frags: ldmatrix.x4.trans.
// ---------------------------------------------------------------------------
#define BKC 32
#define SAH 40
#define SBH 72

template <int OC, bool RESID>
__global__ void __launch_bounds__(256) gemm_mma_kernel(
    const float* __restrict__ W, const float* __restrict__ bias,
    const float* __restrict__ X, const float* __restrict__ R,
    float* __restrict__ Y) {
  __shared__ __align__(16) unsigned short Ahi[128 * SAH];
  __shared__ __align__(16) unsigned short Alo[128 * SAH];
  __shared__ __align__(16) unsigned short Bhi[BKC * SBH];
  __shared__ __align__(16) unsigned short Blo[BKC * SBH];

  const int tid = threadIdx.x, lane = tid & 31, wid = tid >> 5;
  const int wm = wid >> 1, wn = wid & 1;
  const int bz = blockIdx.z;
  const int o0 = blockIdx.y * 128;
  const int t0 = blockIdx.x * 64;
  const float* Xb = X + (size_t)bz * NC * NHW;

  // ldmatrix lane->address offsets
  const int a_r = lane & 15;           // A: row within 16
  const int a_c = (lane >> 4) << 3;    // A: col 0/8
  const int b_g = lane >> 3, b_r = lane & 7;
  const int b_row_off = ((b_g & 1) << 3) + b_r;  // B: k row within 16
  const int b_col_off = (b_g >> 1) << 3;         // B: n col 0/8

  float acc[2][4][4] = {};

#pragma unroll 1
  for (int chunk = 0; chunk < NC / BKC; chunk++) {
    const int kc = chunk * BKC;
    // ---- convert A (weights) 128x32 fp32 -> hi/lo bf16 ----
#pragma unroll
    for (int i = 0; i < 4; i++) {
      const int gi = i * 256 + tid;
      const int row = gi >> 3, c4 = gi & 7;
      float4 wv = *(const float4*)(W + (size_t)(o0 + row) * NC + kc + c4 * 4);
      uint32_t h01 = packbf2(wv.x, wv.y);
      uint32_t h23 = packbf2(wv.z, wv.w);
      float hx0 = __uint_as_float(h01 << 16);
      float hx1 = __uint_as_float(h01 & 0xffff0000u);
      float hx2 = __uint_as_float(h23 << 16);
      float hx3 = __uint_as_float(h23 & 0xffff0000u);
      uint32_t l01 = packbf2(wv.x - hx0, wv.y - hx1);
      uint32_t l23 = packbf2(wv.z - hx2, wv.w - hx3);
      *(uint2*)&Ahi[row * SAH + c4 * 4] = make_uint2(h01, h23);
      *(uint2*)&Alo[row * SAH + c4 * 4] = make_uint2(l01, l23);
    }
    // ---- convert B (activations) 32x64 fp32 -> hi/lo bf16 (K-major rows) ----
#pragma unroll
    for (int i = 0; i < 2; i++) {
      const int gi = i * 256 + tid;
      const int c = gi >> 4, t4 = gi & 15;
      float4 xv = *(const float4*)(Xb + (size_t)(kc + c) * NHW + t0 + t4 * 4);
      uint32_t h01 = packbf2(xv.x, xv.y);
      uint32_t h23 = packbf2(xv.z, xv.w);
      float hx0 = __uint_as_float(h01 << 16);
      float hx1 = __uint_as_float(h01 & 0xffff0000u);
      float hx2 = __uint_as_float(h23 << 16);
      float hx3 = __uint_as_float(h23 & 0xffff0000u);
      uint32_t l01 = packbf2(xv.x - hx0, xv.y - hx1);
      uint32_t l23 = packbf2(xv.z - hx2, xv.w - hx3);
      *(uint2*)&Bhi[c * SBH + t4 * 4] = make_uint2(h01, h23);
      *(uint2*)&Blo[c * SBH + t4 * 4] = make_uint2(l01, l23);
    }
    __syncthreads();

#pragma unroll
    for (int ks = 0; ks < 2; ks++) {
      const int kb = ks * 16;
      uint32_t ah[2][4], al[2][4], bh[2][4], bl[2][4];
#pragma unroll
      for (int mf = 0; mf < 2; mf++) {
        const int arow = (wm * 32 + mf * 16 + a_r) * SAH + kb + a_c;
        ldsm_x4(ah[mf], smem_u32(&Ahi[arow]));
        ldsm_x4(al[mf], smem_u32(&Alo[arow]));
      }
#pragma unroll
      for (int p = 0; p < 2; p++) {
        const int boff =
            (kb + b_row_off) * SBH + wn * 32 + p * 16 + b_col_off;
        ldsm_x4_t(bh[p], smem_u32(&Bhi[boff]));
        ldsm_x4_t(bl[p], smem_u32(&Blo[boff]));
      }
#pragma unroll
      for (int mf = 0; mf < 2; mf++)
#pragma unroll
        for (int p = 0; p < 2; p++) {
          mma16816(acc[mf][2 * p], ah[mf], &bh[p][0]);
          mma16816(acc[mf][2 * p + 1], ah[mf], &bh[p][2]);
          mma16816(acc[mf][2 * p], ah[mf], &bl[p][0]);
          mma16816(acc[mf][2 * p + 1], ah[mf], &bl[p][2]);
          mma16816(acc[mf][2 * p], al[mf], &bh[p][0]);
          mma16816(acc[mf][2 * p + 1], al[mf], &bh[p][2]);
        }
    }
    __syncthreads();
  }

  // ---- epilogue: bias (+residual), direct stores ----
#pragma unroll
  for (int mf = 0; mf < 2; mf++)
#pragma unroll
    for (int nf = 0; nf < 4; nf++) {
      const int o = o0 + wm * 32 + mf * 16 + (lane >> 2);
      const int t = t0 + wn * 32 + nf * 8 + ((lane & 3) << 1);
      const size_t off0 = ((size_t)bz * OC + o) * NHW + t;
      const size_t off1 = off0 + (size_t)8 * NHW;
      const float bi0 = bias[o], bi1 = bias[o + 8];
      float2 v0 = make_float2(acc[mf][nf][0] + bi0, acc[mf][nf][1] + bi0);
      float2 v1 = make_float2(acc[mf][nf][2] + bi1, acc[mf][nf][3] + bi1);
      if (RESID) {
        float2 r0 = *(const float2*)(R + off0);
        float2 r1 = *(const float2*)(R + off1);
        v0.x += r0.x; v0.y += r0.y;
        v1.x += r1.x; v1.y += r1.y;
      }
      *(float2*)(Y + off0) = v0;
      *(float2*)(Y + off1) = v1;
    }
}

// ---------------------------------------------------------------------------
// Flash attention (unchanged from passing R3 version)
// ---------------------------------------------------------------------------
#define SQ 132
#define SK 132
#define SV 68
#define SP 132

__global__ void __launch_bounds__(256, 1) attn_kernel(
    const float* __restrict__ qkv, float* __restrict__ out) {
  extern __shared__ float sm[];
  float* Qs = sm;
  float* Ks = Qs + 64 * SQ;
  float* Vt = Ks + 64 * SK;
  float* Pt = Vt + 128 * SV;

  const int tid = threadIdx.x;
  const int tx = tid & 15, ty = tid >> 4;
  const int warp = tid >> 5, lane = tid & 31;
  const int bh = blockIdx.y;
  const int b = bh >> 3, h = bh & 7;
  const int t0 = blockIdx.x * 128;
  const float scale = 0.125f;

  const float* qb = qkv + ((size_t)b * OC3 + h * HD) * NHW;
  const float* kb_ = qb + (size_t)NC * NHW;
  const float* vb = qb + (size_t)2 * NC * NHW;

#pragma unroll
  for (int it = 0; it < 8; it++) {
    const int d = warp * 8 + it;
    float4 v = *(const float4*)(qb + (size_t)d * NHW + t0 + lane * 4);
    v.x *= scale; v.y *= scale; v.z *= scale; v.w *= scale;
    *(float4*)&Qs[d * SQ + lane * 4] = v;
  }

  float m[8], l[8], o_[8][4];
#pragma unroll
  for (int i = 0; i < 8; i++) {
    m[i] = -1e30f; l[i] = 0.f;
#pragma unroll
    for (int jj = 0; jj < 4; jj++) o_[i][jj] = 0.f;
  }
  __syncthreads();

#pragma unroll 1
  for (int s0 = 0; s0 < NHW; s0 += 128) {
#pragma unroll
    for (int it = 0; it < 8; it++) {
      const int d = warp * 8 + it;
      *(float4*)&Ks[d * SK + lane * 4] =
          *(const float4*)(kb_ + (size_t)d * NHW + s0 + lane * 4);
      float4 vv = *(const float4*)(vb + (size_t)d * NHW + s0 + lane * 4);
      Vt[(lane * 4 + 0) * SV + d] = vv.x;
      Vt[(lane * 4 + 1) * SV + d] = vv.y;
      Vt[(lane * 4 + 2) * SV + d] = vv.z;
      Vt[(lane * 4 + 3) * SV + d] = vv.w;
    }
    __syncthreads();

    float sc[8][8] = {};
#pragma unroll 8
    for (int k = 0; k < 64; k++) {
      float4 a0 = *(const float4*)&Qs[k * SQ + ty * 8];
      float4 a1 = *(const float4*)&Qs[k * SQ + ty * 8 + 4];
      float4 b0 = *(const float4*)&Ks[k * SK + tx * 8];
      float4 b1 = *(const float4*)&Ks[k * SK + tx * 8 + 4];
      float av[8] = {a0.x, a0.y, a0.z, a0.w, a1.x, a1.y, a1.z, a1.w};
      float bv[8] = {b0.x, b0.y, b0.z, b0.w, b1.x, b1.y, b1.z, b1.w};
#pragma unroll
      for (int i = 0; i < 8; i++)
#pragma unroll
        for (int j = 0; j < 8; j++) sc[i][j] += av[i] * bv[j];
    }

#pragma unroll
    for (int i = 0; i < 8; i++) {
      float mt = sc[i][0];
#pragma unroll
      for (int j = 1; j < 8; j++) mt = fmaxf(mt, sc[i][j]);
#pragma unroll
      for (int off = 8; off; off >>= 1)
        mt = fmaxf(mt, __shfl_xor_sync(0xffffffffu, mt, off));
      const float mn = fmaxf(m[i], mt);
      const float fac = __expf(m[i] - mn);
      m[i] = mn;
      float rs = 0.f;
#pragma unroll
      for (int j = 0; j < 8; j++) {
        const float p = __expf(sc[i][j] - mn);
        sc[i][j] = p;
        rs += p;
      }
#pragma unroll
      for (int off = 8; off; off >>= 1)
        rs += __shfl_xor_sync(0xffffffffu, rs, off);
      l[i] = l[i] * fac + rs;
#pragma unroll
      for (int jj = 0; jj < 4; jj++) o_[i][jj] *= fac;
    }

#pragma unroll
    for (int j = 0; j < 8; j++) {
      const int srow = (tx * 8 + j) * SP + ty * 8;
      *(float4*)&Pt[srow] = make_float4(sc[0][j], sc[1][j], sc[2][j], sc[3][j]);
      *(float4*)&Pt[srow + 4] =
          make_float4(sc[4][j], sc[5][j], sc[6][j], sc[7][j]);
    }
    __syncthreads();

#pragma unroll 4
    for (int s = 0; s < 128; s++) {
      float4 a0 = *(const float4*)&Pt[s * SP + ty * 8];
      float4 a1 = *(const float4*)&Pt[s * SP + ty * 8 + 4];
      float4 bvv = *(const float4*)&Vt[s * SV + tx * 4];
      float av[8] = {a0.x, a0.y, a0.z, a0.w, a1.x, a1.y, a1.z, a1.w};
      float bv[4] = {bvv.x, bvv.y, bvv.z, bvv.w};
#pragma unroll
      for (int i = 0; i < 8; i++)
#pragma unroll
        for (int jj = 0; jj < 4; jj++) o_[i][jj] += av[i] * bv[jj];
    }
    __syncthreads();
  }

  float inv[8];
#pragma unroll
  for (int i = 0; i < 8; i++) inv[i] = 1.f / l[i];
#pragma unroll
  for (int jj = 0; jj < 4; jj++)
#pragma unroll
    for (int i = 0; i < 8; i++)
      Pt[(tx * 4 + jj) * SP + ty * 8 + i] = o_[i][jj] * inv[i];
  __syncthreads();
#pragma unroll
  for (int it = 0; it < 8; it++) {
    const int d = warp * 8 + it;
    float4 v = *(const float4*)&Pt[d * SP + lane * 4];
    *(float4*)(out + ((size_t)b * NC + h * HD + d) * NHW + t0 + lane * 4) = v;
  }
}

// ---------------------------------------------------------------------------
extern "C" void kernel_launch(void* const* d_in, const int* in_sizes, int n_in,
                              void* d_out, int out_size) {
  const float* x = (const float*)d_in[0];
  const float* gn_gamma = (const float*)d_in[1];
  const float* gn_beta = (const float*)d_in[2];
  const float* qkv_w = (const float*)d_in[3];
  const float* qkv_b = (const float*)d_in[4];
  const float* proj_w = (const float*)d_in[5];
  const float* proj_b = (const float*)d_in[6];
  float* out = (float*)d_out;

  float *xn, *qkvp, *att;
  cudaGetSymbolAddress((void**)&xn, g_xn);
  cudaGetSymbolAddress((void**)&qkvp, g_qkv);
  cudaGetSymbolAddress((void**)&att, g_att);

  const int ATT_SMEM =
      (64 * SQ + 64 * SK + 128 * SV + 128 * SP) * (int)sizeof(float);
  cudaFuncSetAttribute(attn_kernel, cudaFuncAttributeMaxDynamicSharedMemorySize,
                       ATT_SMEM);

  gn_kernel<<<NB * NG, 256>>>(x, gn_gamma, gn_beta, xn);
  gemm_mma_kernel<OC3, false>
      <<<dim3(16, 12, NB), 256>>>(qkv_w, qkv_b, xn, nullptr, qkvp);
  attn_kernel<<<dim3(8, NB * NHEADS), 256, ATT_SMEM>>>(qkvp, att);
  gemm_mma_kernel<NC, true>
      <<<dim3(16, 4, NB), 256>>>(proj_w, proj_b, att, x, out);
}

// round 8
// speedup vs baseline: 2.5863x; 1.8604x over previous
#include <cuda_runtime.h>
#include <math.h>
#include <stdint.h>

#define NB 16
#define NC 512
#define NHW 1024
#define NHEADS 8
#define HD 64
#define NG 32
#define OC3 1536
#define GN_EPS 1e-5f

typedef unsigned short ushort_t;

// Scratch (static device globals — allocation-free per harness rules)
__device__ ushort_t g_wqhi[(size_t)OC3 * NC];
__device__ ushort_t g_wqlo[(size_t)OC3 * NC];
__device__ ushort_t g_wphi[(size_t)NC * NC];
__device__ ushort_t g_wplo[(size_t)NC * NC];
__device__ ushort_t g_xnhi[(size_t)NB * NC * NHW];
__device__ ushort_t g_xnlo[(size_t)NB * NC * NHW];
__device__ ushort_t g_qkvhi[(size_t)NB * OC3 * NHW];
__device__ ushort_t g_qkvlo[(size_t)NB * OC3 * NHW];
__device__ ushort_t g_atthi[(size_t)NB * NC * NHW];
__device__ ushort_t g_attlo[(size_t)NB * NC * NHW];

// ============================ helpers ======================================
__device__ __forceinline__ uint32_t smem_u32(const void* p) {
  uint32_t a;
  asm("{ .reg .u64 t; cvta.to.shared.u64 t, %1; cvt.u32.u64 %0, t; }"
      : "=r"(a) : "l"(p));
  return a;
}
__device__ __forceinline__ uint32_t packbf2(float lo16, float hi16) {
  // low 16 bits = bf16(lo16), high 16 bits = bf16(hi16)
  uint32_t r;
  asm("cvt.rn.bf16x2.f32 %0, %1, %2;" : "=r"(r) : "f"(hi16), "f"(lo16));
  return r;
}
__device__ __forceinline__ float bflo_f(uint32_t u) {  // float of low half
  return __uint_as_float(u << 16);
}
__device__ __forceinline__ float bfhi_f(uint32_t u) {  // float of high half
  return __uint_as_float(u & 0xffff0000u);
}
__device__ __forceinline__ void ldsm_x4(uint32_t* r, uint32_t addr) {
  asm volatile("ldmatrix.sync.aligned.m8n8.x4.shared.b16 {%0,%1,%2,%3}, [%4];"
               : "=r"(r[0]), "=r"(r[1]), "=r"(r[2]), "=r"(r[3]) : "r"(addr));
}
__device__ __forceinline__ void ldsm_x4_t(uint32_t* r, uint32_t addr) {
  asm volatile(
      "ldmatrix.sync.aligned.m8n8.x4.trans.shared.b16 {%0,%1,%2,%3}, [%4];"
      : "=r"(r[0]), "=r"(r[1]), "=r"(r[2]), "=r"(r[3]) : "r"(addr));
}
__device__ __forceinline__ void mma16816(float* d, const uint32_t* a,
                                         const uint32_t* b) {
  asm volatile(
      "mma.sync.aligned.m16n8k16.row.col.f32.bf16.bf16.f32 "
      "{%0,%1,%2,%3}, {%4,%5,%6,%7}, {%8,%9}, {%0,%1,%2,%3};"
      : "+f"(d[0]), "+f"(d[1]), "+f"(d[2]), "+f"(d[3])
      : "r"(a[0]), "r"(a[1]), "r"(a[2]), "r"(a[3]), "r"(b[0]), "r"(b[1]));
}

// ---------------------------------------------------------------------------
// Weight prep: fp32 -> hi/lo bf16 planes (once per launch, not per CTA)
// ---------------------------------------------------------------------------
__global__ void __launch_bounds__(256) prep_w_kernel(
    const float* __restrict__ qkv_w, const float* __restrict__ proj_w) {
  const int idx = blockIdx.x * 256 + threadIdx.x;  // one float4 each
  const int nq = OC3 * NC / 4;
  const float* src;
  ushort_t *dh, *dl;
  int off;
  if (idx < nq) {
    src = qkv_w; dh = g_wqhi; dl = g_wqlo; off = idx * 4;
  } else {
    src = proj_w; dh = g_wphi; dl = g_wplo; off = (idx - nq) * 4;
  }
  float4 v = *(const float4*)(src + off);
  uint32_t h01 = packbf2(v.x, v.y), h23 = packbf2(v.z, v.w);
  uint32_t l01 = packbf2(v.x - bflo_f(h01), v.y - bfhi_f(h01));
  uint32_t l23 = packbf2(v.z - bflo_f(h23), v.w - bfhi_f(h23));
  *(uint2*)(dh + off) = make_uint2(h01, h23);
  *(uint2*)(dl + off) = make_uint2(l01, l23);
}

// ---------------------------------------------------------------------------
// GroupNorm -> hi/lo bf16 planes
// ---------------------------------------------------------------------------
__global__ void __launch_bounds__(256) gn_kernel(
    const float* __restrict__ x, const float* __restrict__ gamma,
    const float* __restrict__ beta) {
  const int bg = blockIdx.x;
  const int g = bg & (NG - 1);
  const size_t base = (size_t)bg * (NC / NG) * NHW;
  const float* px = x + base;
  ushort_t* poh = g_xnhi + base;
  ushort_t* pol = g_xnlo + base;
  const int tid = threadIdx.x;

  float s = 0.f, q = 0.f;
#pragma unroll
  for (int k = 0; k < 16; k++) {
    float4 v = *(const float4*)(px + (size_t)(tid + k * 256) * 4);
    s += v.x + v.y + v.z + v.w;
    q += v.x * v.x + v.y * v.y + v.z * v.z + v.w * v.w;
  }
#pragma unroll
  for (int off = 16; off; off >>= 1) {
    s += __shfl_xor_sync(0xffffffffu, s, off);
    q += __shfl_xor_sync(0xffffffffu, q, off);
  }
  __shared__ float ss[8], sq[8];
  __shared__ float s_mean, s_inv;
  const int w = tid >> 5;
  if ((tid & 31) == 0) { ss[w] = s; sq[w] = q; }
  __syncthreads();
  if (tid == 0) {
    float ts = 0.f, tq = 0.f;
#pragma unroll
    for (int i = 0; i < 8; i++) { ts += ss[i]; tq += sq[i]; }
    float mean = ts * (1.f / 16384.f);
    float var = tq * (1.f / 16384.f) - mean * mean;
    s_mean = mean;
    s_inv = rsqrtf(var + GN_EPS);
  }
  __syncthreads();
  const float mean = s_mean, inv = s_inv;
#pragma unroll
  for (int k = 0; k < 16; k++) {
    size_t off = (size_t)(tid + k * 256) * 4;
    int c = g * 16 + (int)(off >> 10);
    float ga = gamma[c], be = beta[c];
    float4 v = *(const float4*)(px + off);
    v.x = (v.x - mean) * inv * ga + be;
    v.y = (v.y - mean) * inv * ga + be;
    v.z = (v.z - mean) * inv * ga + be;
    v.w = (v.w - mean) * inv * ga + be;
    uint32_t h01 = packbf2(v.x, v.y), h23 = packbf2(v.z, v.w);
    uint32_t l01 = packbf2(v.x - bflo_f(h01), v.y - bfhi_f(h01));
    uint32_t l23 = packbf2(v.z - bflo_f(h23), v.w - bfhi_f(h23));
    *(uint2*)(poh + off) = make_uint2(h01, h23);
    *(uint2*)(pol + off) = make_uint2(l01, l23);
  }
}

// ---------------------------------------------------------------------------
// bf16 GEMM (3-term split): Y[b][o][t] = sum_c W[o][c] X[b][c][t] + bias
// Tile 128(o) x 128(t), K-chunk 32; 8 warps = 4m x 2n; warp 32x64.
// EMIT_BF16: emit hi/lo bf16 planes. Else fp32 + residual.
// ---------------------------------------------------------------------------
#define SAH 40
#define SBH 136

template <int OC, bool EMIT>
__global__ void __launch_bounds__(256) gemm_bf16_kernel(
    const ushort_t* __restrict__ Ahi, const ushort_t* __restrict__ Alo,
    const float* __restrict__ bias, const ushort_t* __restrict__ Bhi,
    const ushort_t* __restrict__ Blo, const float* __restrict__ R,
    float* __restrict__ Yf, ushort_t* __restrict__ Yhi,
    ushort_t* __restrict__ Ylo) {
  __shared__ __align__(16) ushort_t As[2][128 * SAH];
  __shared__ __align__(16) ushort_t Bs[2][32 * SBH];

  const int tid = threadIdx.x, lane = tid & 31, wid = tid >> 5;
  const int wm = wid >> 1, wn = wid & 1;
  const int bz = blockIdx.z;
  const int o0 = blockIdx.y * 128;
  const int t0 = blockIdx.x * 128;
  const size_t bb = (size_t)bz * NC * NHW;

  const int a_r = lane & 15, a_c = (lane >> 4) << 3;
  const int b_g = lane >> 3;
  const int b_row = ((b_g & 1) << 3) + (lane & 7);
  const int b_col = (b_g >> 1) << 3;

  float acc[2][8][4] = {};

#pragma unroll 1
  for (int chunk = 0; chunk < NC / 32; chunk++) {
    const int kc = chunk * 32;
#pragma unroll
    for (int i = 0; i < 4; i++) {
      const int idx = i * 256 + tid;
      const int pl = idx >> 9, r = (idx >> 2) & 127, c = idx & 3;
      const ushort_t* src =
          (pl ? Alo : Ahi) + (size_t)(o0 + r) * NC + kc + c * 8;
      *(uint4*)&As[pl][r * SAH + c * 8] = *(const uint4*)src;
    }
#pragma unroll
    for (int i = 0; i < 4; i++) {
      const int idx = i * 256 + tid;
      const int pl = idx >> 9, r = (idx >> 4) & 31, c = idx & 15;
      const ushort_t* src =
          (pl ? Blo : Bhi) + bb + (size_t)(kc + r) * NHW + t0 + c * 8;
      *(uint4*)&Bs[pl][r * SBH + c * 8] = *(const uint4*)src;
    }
    __syncthreads();
#pragma unroll
    for (int ks = 0; ks < 2; ks++) {
      const int kb = ks * 16;
      uint32_t ah[2][4], al[2][4];
#pragma unroll
      for (int mf = 0; mf < 2; mf++) {
        const int ao = (wm * 32 + mf * 16 + a_r) * SAH + kb + a_c;
        ldsm_x4(ah[mf], smem_u32(&As[0][ao]));
        ldsm_x4(al[mf], smem_u32(&As[1][ao]));
      }
#pragma unroll
      for (int nb = 0; nb < 4; nb++) {
        uint32_t bh[4], bl[4];
        const int bo = (kb + b_row) * SBH + wn * 64 + nb * 16 + b_col;
        ldsm_x4_t(bh, smem_u32(&Bs[0][bo]));
        ldsm_x4_t(bl, smem_u32(&Bs[1][bo]));
#pragma unroll
        for (int mf = 0; mf < 2; mf++) {
          mma16816(acc[mf][2 * nb], ah[mf], &bh[0]);
          mma16816(acc[mf][2 * nb + 1], ah[mf], &bh[2]);
          mma16816(acc[mf][2 * nb], ah[mf], &bl[0]);
          mma16816(acc[mf][2 * nb + 1], ah[mf], &bl[2]);
          mma16816(acc[mf][2 * nb], al[mf], &bh[0]);
          mma16816(acc[mf][2 * nb + 1], al[mf], &bh[2]);
        }
      }
    }
    __syncthreads();
  }

#pragma unroll
  for (int mf = 0; mf < 2; mf++)
#pragma unroll
    for (int nf = 0; nf < 8; nf++) {
      const int o = o0 + wm * 32 + mf * 16 + (lane >> 2);
      const int t = t0 + wn * 64 + nf * 8 + ((lane & 3) << 1);
      const size_t off0 = ((size_t)bz * OC + o) * NHW + t;
      const size_t off1 = off0 + (size_t)8 * NHW;
      const float bi0 = bias[o], bi1 = bias[o + 8];
      float y0 = acc[mf][nf][0] + bi0, y1 = acc[mf][nf][1] + bi0;
      float y2 = acc[mf][nf][2] + bi1, y3 = acc[mf][nf][3] + bi1;
      if (EMIT) {
        uint32_t h01 = packbf2(y0, y1), h23 = packbf2(y2, y3);
        uint32_t l01 = packbf2(y0 - bflo_f(h01), y1 - bfhi_f(h01));
        uint32_t l23 = packbf2(y2 - bflo_f(h23), y3 - bfhi_f(h23));
        *(uint32_t*)(Yhi + off0) = h01;
        *(uint32_t*)(Yhi + off1) = h23;
        *(uint32_t*)(Ylo + off0) = l01;
        *(uint32_t*)(Ylo + off1) = l23;
      } else {
        float2 r0 = *(const float2*)(R + off0);
        float2 r1 = *(const float2*)(R + off1);
        *(float2*)(Yf + off0) = make_float2(y0 + r0.x, y1 + r0.y);
        *(float2*)(Yf + off1) = make_float2(y2 + r1.x, y3 + r1.y);
      }
    }
}

// ---------------------------------------------------------------------------
// Flash attention on mma.sync (3-term split QK and PV).
// Block: (b,h, t-tile 128). 8 warps x m16. s streamed in 128 tiles.
// smem halves: Q[64][136] x2, K[64][136] x2, V[128][72] x2.
// ---------------------------------------------------------------------------
#define AQH 136
#define AVH 72

__global__ void __launch_bounds__(256, 1) attn_mma_kernel(
    const ushort_t* __restrict__ qkvhi, const ushort_t* __restrict__ qkvlo,
    ushort_t* __restrict__ outhi, ushort_t* __restrict__ outlo) {
  extern __shared__ __align__(16) ushort_t smem[];
  ushort_t* Qh = smem;                // 64*136
  ushort_t* Ql = Qh + 64 * AQH;
  ushort_t* Kh = Ql + 64 * AQH;
  ushort_t* Kl = Kh + 64 * AQH;
  ushort_t* Vh = Kl + 64 * AQH;       // 128*72
  ushort_t* Vl = Vh + 128 * AVH;

  const int tid = threadIdx.x, lane = tid & 31, warp = tid >> 5;
  const int bh_ = blockIdx.y;
  const int b = bh_ >> 3, h = bh_ & 7;
  const int t0 = blockIdx.x * 128;

  const ushort_t* qh = qkvhi + ((size_t)b * OC3 + h * HD) * NHW;
  const ushort_t* ql = qkvlo + ((size_t)b * OC3 + h * HD) * NHW;
  const ushort_t* kh = qh + (size_t)NC * NHW;
  const ushort_t* kl = ql + (size_t)NC * NHW;
  const ushort_t* vh = qh + (size_t)2 * NC * NHW;
  const ushort_t* vl = ql + (size_t)2 * NC * NHW;

  // Load Q tiles: [d 64][t 128] halves, 2 planes
#pragma unroll
  for (int i = 0; i < 8; i++) {
    const int idx = i * 256 + tid;
    const int pl = idx >> 10, r = (idx >> 4) & 63, c = idx & 15;
    ushort_t* dst = (pl ? Ql : Qh) + r * AQH + c * 8;
    const ushort_t* src = (pl ? ql : qh) + (size_t)r * NHW + t0 + c * 8;
    *(uint4*)dst = *(const uint4*)src;
  }
  __syncthreads();

  // Hoist Q A-fragments (trans load from [k=d][m=t])
  const int a_kr = ((lane >> 4) << 3) + (lane & 7);
  const int a_mc = ((lane >> 3) & 1) << 3;
  uint32_t aq[4][4], aql[4][4];
#pragma unroll
  for (int k4 = 0; k4 < 4; k4++) {
    const int ao = (k4 * 16 + a_kr) * AQH + warp * 16 + a_mc;
    ldsm_x4_t(aq[k4], smem_u32(&Qh[ao]));
    ldsm_x4_t(aql[k4], smem_u32(&Ql[ao]));
  }

  const int b_g = lane >> 3;
  const int b_row = ((b_g & 1) << 3) + (lane & 7);
  const int b_col = (b_g >> 1) << 3;

  float o8[8][4] = {};
  float m0 = -1e30f, m1 = -1e30f, l0 = 0.f, l1 = 0.f;

#pragma unroll 1
  for (int s0 = 0; s0 < NHW; s0 += 128) {
    // K tile: [d][s] halves
#pragma unroll
    for (int i = 0; i < 8; i++) {
      const int idx = i * 256 + tid;
      const int pl = idx >> 10, r = (idx >> 4) & 63, c = idx & 15;
      ushort_t* dst = (pl ? Kl : Kh) + r * AQH + c * 8;
      const ushort_t* src = (pl ? kl : kh) + (size_t)r * NHW + s0 + c * 8;
      *(uint4*)dst = *(const uint4*)src;
    }
    // V tile transposed: [s][d]; dp-major lanes -> conflict-free STS
#pragma unroll
    for (int i = 0; i < 4; i++) {
      const int idx = i * 256 + tid;
      const int pl = idx >> 9, u = idx & 511;
      const int dp = u & 31, sc = u >> 5;
      const ushort_t* src = pl ? vl : vh;
      ushort_t* dst = pl ? Vl : Vh;
      uint4 r0 = *(const uint4*)(src + (size_t)(2 * dp) * NHW + s0 + sc * 8);
      uint4 r1 = *(const uint4*)(src + (size_t)(2 * dp + 1) * NHW + s0 + sc * 8);
      uint32_t q0[4] = {r0.x, r0.y, r0.z, r0.w};
      uint32_t q1[4] = {r1.x, r1.y, r1.z, r1.w};
#pragma unroll
      for (int j2 = 0; j2 < 4; j2++) {
        uint32_t a = q0[j2], bq = q1[j2];
        uint32_t w0 = (a & 0xffffu) | (bq << 16);
        uint32_t w1 = (a >> 16) | (bq & 0xffff0000u);
        const int s = sc * 8 + 2 * j2;
        *(uint32_t*)&dst[s * AVH + 2 * dp] = w0;
        *(uint32_t*)&dst[(s + 1) * AVH + 2 * dp] = w1;
      }
    }
    __syncthreads();

    // ---- S = Q^T K (m16 x n128, k=64) ----
    float sacc[16][4] = {};
#pragma unroll
    for (int k4 = 0; k4 < 4; k4++) {
#pragma unroll
      for (int nb = 0; nb < 8; nb++) {
        uint32_t bh[4], bl[4];
        const int bo = (k4 * 16 + b_row) * AQH + nb * 16 + b_col;
        ldsm_x4_t(bh, smem_u32(&Kh[bo]));
        ldsm_x4_t(bl, smem_u32(&Kl[bo]));
        mma16816(sacc[2 * nb], aq[k4], &bh[0]);
        mma16816(sacc[2 * nb + 1], aq[k4], &bh[2]);
        mma16816(sacc[2 * nb], aq[k4], &bl[0]);
        mma16816(sacc[2 * nb + 1], aq[k4], &bl[2]);
        mma16816(sacc[2 * nb], aql[k4], &bh[0]);
        mma16816(sacc[2 * nb + 1], aql[k4], &bh[2]);
      }
    }

    // ---- scale + online softmax (rows g=lane>>2 and g+8) ----
#pragma unroll
    for (int f = 0; f < 16; f++) {
      sacc[f][0] *= 0.125f; sacc[f][1] *= 0.125f;
      sacc[f][2] *= 0.125f; sacc[f][3] *= 0.125f;
    }
    float mt0 = -1e30f, mt1 = -1e30f;
#pragma unroll
    for (int f = 0; f < 16; f++) {
      mt0 = fmaxf(mt0, fmaxf(sacc[f][0], sacc[f][1]));
      mt1 = fmaxf(mt1, fmaxf(sacc[f][2], sacc[f][3]));
    }
    mt0 = fmaxf(mt0, __shfl_xor_sync(0xffffffffu, mt0, 1));
    mt0 = fmaxf(mt0, __shfl_xor_sync(0xffffffffu, mt0, 2));
    mt1 = fmaxf(mt1, __shfl_xor_sync(0xffffffffu, mt1, 1));
    mt1 = fmaxf(mt1, __shfl_xor_sync(0xffffffffu, mt1, 2));
    const float mn0 = fmaxf(m0, mt0), mn1 = fmaxf(m1, mt1);
    const float fac0 = __expf(m0 - mn0), fac1 = __expf(m1 - mn1);
    m0 = mn0; m1 = mn1;
    float rs0 = 0.f, rs1 = 0.f;
#pragma unroll
    for (int f = 0; f < 16; f++) {
      sacc[f][0] = __expf(sacc[f][0] - mn0);
      sacc[f][1] = __expf(sacc[f][1] - mn0);
      sacc[f][2] = __expf(sacc[f][2] - mn1);
      sacc[f][3] = __expf(sacc[f][3] - mn1);
      rs0 += sacc[f][0] + sacc[f][1];
      rs1 += sacc[f][2] + sacc[f][3];
    }
    rs0 += __shfl_xor_sync(0xffffffffu, rs0, 1);
    rs0 += __shfl_xor_sync(0xffffffffu, rs0, 2);
    rs1 += __shfl_xor_sync(0xffffffffu, rs1, 1);
    rs1 += __shfl_xor_sync(0xffffffffu, rs1, 2);
    l0 = l0 * fac0 + rs0;
    l1 = l1 * fac1 + rs1;
#pragma unroll
    for (int f = 0; f < 8; f++) {
      o8[f][0] *= fac0; o8[f][1] *= fac0;
      o8[f][2] *= fac1; o8[f][3] *= fac1;
    }

    // ---- pack P (S frags -> A frags) ----
    uint32_t Ph[32], Pl[32];
#pragma unroll
    for (int f = 0; f < 16; f++) {
      uint32_t h01 = packbf2(sacc[f][0], sacc[f][1]);
      uint32_t h23 = packbf2(sacc[f][2], sacc[f][3]);
      Ph[2 * f] = h01;
      Ph[2 * f + 1] = h23;
      Pl[2 * f] = packbf2(sacc[f][0] - bflo_f(h01), sacc[f][1] - bfhi_f(h01));
      Pl[2 * f + 1] =
          packbf2(sacc[f][2] - bflo_f(h23), sacc[f][3] - bfhi_f(h23));
    }

    // ---- O += P V (m16 x n64, k=128) ----
#pragma unroll
    for (int k8 = 0; k8 < 8; k8++) {
      const uint32_t* pa = &Ph[4 * k8];
      const uint32_t* pb = &Pl[4 * k8];
#pragma unroll
      for (int nb = 0; nb < 4; nb++) {
        uint32_t vhf[4], vlf[4];
        const int vo = (k8 * 16 + b_row) * AVH + nb * 16 + b_col;
        ldsm_x4_t(vhf, smem_u32(&Vh[vo]));
        ldsm_x4_t(vlf, smem_u32(&Vl[vo]));
        mma16816(o8[2 * nb], pa, &vhf[0]);
        mma16816(o8[2 * nb + 1], pa, &vhf[2]);
        mma16816(o8[2 * nb], pa, &vlf[0]);
        mma16816(o8[2 * nb + 1], pa, &vlf[2]);
        mma16816(o8[2 * nb], pb, &vhf[0]);
        mma16816(o8[2 * nb + 1], pb, &vhf[2]);
      }
    }
    __syncthreads();
  }

  // ---- epilogue: normalize, stage [d][t] f32 in smem, emit hi/lo bf16 ----
  const float inv0 = 1.f / l0, inv1 = 1.f / l1;
  float* Ost = (float*)Qh;  // 64*132 f32 fits in Qh+Ql area
  const int tl0 = warp * 16 + (lane >> 2);
#pragma unroll
  for (int f = 0; f < 8; f++) {
    const int d = f * 8 + ((lane & 3) << 1);
    Ost[d * 132 + tl0] = o8[f][0] * inv0;
    Ost[(d + 1) * 132 + tl0] = o8[f][1] * inv0;
    Ost[d * 132 + tl0 + 8] = o8[f][2] * inv1;
    Ost[(d + 1) * 132 + tl0 + 8] = o8[f][3] * inv1;
  }
  __syncthreads();
#pragma unroll
  for (int i = 0; i < 4; i++) {
    const int idx = i * 256 + tid;
    const int r = idx >> 4, c = idx & 15;
    const float* src = &Ost[r * 132 + c * 8];
    uint32_t hu[4], lu[4];
#pragma unroll
    for (int j = 0; j < 4; j++) {
      float v0 = src[2 * j], v1 = src[2 * j + 1];
      hu[j] = packbf2(v0, v1);
      lu[j] = packbf2(v0 - bflo_f(hu[j]), v1 - bfhi_f(hu[j]));
    }
    const size_t off = ((size_t)b * NC + h * HD + r) * NHW + t0 + c * 8;
    *(uint4*)(outhi + off) = make_uint4(hu[0], hu[1], hu[2], hu[3]);
    *(uint4*)(outlo + off) = make_uint4(lu[0], lu[1], lu[2], lu[3]);
  }
}

// ---------------------------------------------------------------------------
extern "C" void kernel_launch(void* const* d_in, const int* in_sizes, int n_in,
                              void* d_out, int out_size) {
  const float* x = (const float*)d_in[0];
  const float* gn_gamma = (const float*)d_in[1];
  const float* gn_beta = (const float*)d_in[2];
  const float* qkv_w = (const float*)d_in[3];
  const float* qkv_b = (const float*)d_in[4];
  const float* proj_w = (const float*)d_in[5];
  const float* proj_b = (const float*)d_in[6];
  float* out = (float*)d_out;

  ushort_t *wqh, *wql, *wph, *wpl, *xnh, *xnl, *qh, *qlo, *ath, *atl;
  cudaGetSymbolAddress((void**)&wqh, g_wqhi);
  cudaGetSymbolAddress((void**)&wql, g_wqlo);
  cudaGetSymbolAddress((void**)&wph, g_wphi);
  cudaGetSymbolAddress((void**)&wpl, g_wplo);
  cudaGetSymbolAddress((void**)&xnh, g_xnhi);
  cudaGetSymbolAddress((void**)&xnl, g_xnlo);
  cudaGetSymbolAddress((void**)&qh, g_qkvhi);
  cudaGetSymbolAddress((void**)&qlo, g_qkvlo);
  cudaGetSymbolAddress((void**)&ath, g_atthi);
  cudaGetSymbolAddress((void**)&atl, g_attlo);

  const int ATT_SMEM = (4 * 64 * AQH + 2 * 128 * AVH) * (int)sizeof(ushort_t);
  cudaFuncSetAttribute(attn_mma_kernel,
                       cudaFuncAttributeMaxDynamicSharedMemorySize, ATT_SMEM);

  gn_kernel<<<NB * NG, 256>>>(x, gn_gamma, gn_beta);
  prep_w_kernel<<<(OC3 * NC + NC * NC) / 4 / 256, 256>>>(qkv_w, proj_w);
  gemm_bf16_kernel<OC3, true><<<dim3(8, 12, NB), 256>>>(
      wqh, wql, qkv_b, xnh, xnl, nullptr, nullptr, qh, qlo);
  attn_mma_kernel<<<dim3(8, NB * NHEADS), 256, ATT_SMEM>>>(qh, qlo, ath, atl);
  gemm_bf16_kernel<NC, false><<<dim3(8, 4, NB), 256>>>(
      wph, wpl, proj_b, ath, atl, x, out, nullptr, nullptr);
}